// round 15
// baseline (speedup 1.0000x reference)
#include <cuda_runtime.h>
#include <cuda_fp16.h>
#include <cstdint>

// Problem constants (fixed shapes per reference)
#define M_TOK   65536          // N*L = 16*4096
#define FEATD   512
#define H1D     1024
#define NAA     21
#define CRD     42             // 14*3
#define EPSF    1e-6f
#define MAXBLK  533            // 65536/128 + 21 (padded 128-token groups)

// -------- static device scratch (no runtime allocation allowed) ----------
__device__ unsigned g_crdh[(size_t)M_TOK * 21];        // packed half2 crd
__device__ float    g_table[NAA * H1D];                // embed[aa]@w1[882:]+b1
__device__ __half   g_h1h[(size_t)M_TOK * H1D];        // 128 MB  (fp16 h1)
__device__ __half   g_h2h[(size_t)M_TOK * FEATD];      // 64 MB
// W packed as [n][k2] (K-major per column, half2 along k)
__device__ unsigned g_w2p[(size_t)FEATD * (H1D/2)];    // 262144 packed half2
__device__ unsigned g_w3p[(size_t)FEATD * (FEATD/2)];  // 131072
__device__ unsigned g_w4p[(size_t)FEATD * (FEATD/2)];  // 131072
__device__ int      g_mask_mode;
// sorting scratch
__device__ int      g_histp[64][NAA];
__device__ unsigned g_mflag[64];
__device__ int      g_hist[NAA];
__device__ int      g_cnt[NAA];
__device__ int      g_base[NAA];
__device__ int      g_blk_aa[MAXBLK];
__device__ int      g_perm[MAXBLK * 128];

// ---------------------------------------------------------------------------
__device__ __forceinline__ uint32_t smem_u32(const void* p)
{
    uint32_t a;
    asm("{ .reg .u64 t; cvta.to.shared.u64 t, %1; cvt.u32.u64 %0, t; }"
        : "=r"(a) : "l"(p));
    return a;
}

#define CP_ASYNC16(dst, src) \
    asm volatile("cp.async.cg.shared.global [%0], [%1], 16;" \
                 :: "r"(dst), "l"(src) : "memory")
#define CP_COMMIT()  asm volatile("cp.async.commit_group;" ::: "memory")
#define CP_WAIT(n)   asm volatile("cp.async.wait_group %0;" :: "n"(n) : "memory")

#define LDSM_X4(R0, R1, R2, R3, ADDR) \
    asm volatile("ldmatrix.sync.aligned.m8n8.x4.shared.b16 {%0,%1,%2,%3}, [%4];" \
        : "=r"(R0), "=r"(R1), "=r"(R2), "=r"(R3) : "r"(ADDR))

#define MMA16816(ACC, AF, B0, B1)                                              \
    asm volatile(                                                              \
        "mma.sync.aligned.m16n8k16.row.col.f32.f16.f16.f32 "                   \
        "{%0,%1,%2,%3}, {%4,%5,%6,%7}, {%8,%9}, {%0,%1,%2,%3};"                \
        : "+f"((ACC)[0]), "+f"((ACC)[1]), "+f"((ACC)[2]), "+f"((ACC)[3])       \
        : "r"((AF)[0]), "r"((AF)[1]), "r"((AF)[2]), "r"((AF)[3]),              \
          "r"(B0), "r"(B1))

__device__ __forceinline__ unsigned pack_h2(float a, float b)
{
    __half2 h = __floats2half2_rn(a, b);
    return *(unsigned*)&h;
}

// ---------------------------------------------------------------------------
// Fused mask-sniff + per-block histogram. 64 blocks x 256.
// ---------------------------------------------------------------------------
__global__ void __launch_bounds__(256) prep_kernel(
    const unsigned int* __restrict__ maskw, const int* __restrict__ aa)
{
    __shared__ int h[NAA];
    __shared__ unsigned fl;
    const int tid = threadIdx.x;
    const int b   = blockIdx.x;
    if (tid < NAA) h[tid] = 0;
    if (tid == 0)  fl = 0;
    __syncthreads();

    int base = b * 1024;
    for (int j = tid; j < 1024; j += 256) atomicAdd(&h[aa[base + j]], 1);
    if (tid < 64) {
        unsigned v = maskw[b * 64 + tid];
        if (v == 0x3F800000u) atomicOr(&fl, 1u);
        else if (v > 1u)      atomicOr(&fl, 2u);
    }
    __syncthreads();
    if (tid < NAA) g_histp[b][tid] = h[tid];
    if (tid == 0)  g_mflag[b] = fl;
}

// ---------------------------------------------------------------------------
// Scan
// ---------------------------------------------------------------------------
__global__ void __launch_bounds__(256) scan_kernel()
{
    __shared__ int sbase[NAA], snb[NAA];
    const int tid = threadIdx.x;

    for (int a = tid; a < NAA; a += 256) {
        int s = 0;
        #pragma unroll 8
        for (int b = 0; b < 64; b++) s += g_histp[b][a];
        g_hist[a] = s;
        g_cnt[a]  = 0;
    }
    if (tid == 0) {
        unsigned f = 0;
        for (int b = 0; b < 64; b++) f |= g_mflag[b];
        g_mask_mode = (f & 1u) ? 1 : ((f & 2u) ? 2 : 0);
    }
    __syncthreads();

    if (tid == 0) {
        int cur = 0;
        for (int a = 0; a < NAA; a++) {
            sbase[a] = cur >> 7;
            int nb = (g_hist[a] + 127) >> 7;
            snb[a] = nb;
            g_base[a] = cur;
            cur += nb << 7;
        }
    }
    __syncthreads();

    for (int b = tid; b < MAXBLK; b += 256) {
        int av = -1;
        #pragma unroll
        for (int a = 0; a < NAA; a++)
            if (b >= sbase[a] && b < sbase[a] + snb[a]) av = a;
        g_blk_aa[b] = av;
    }
    for (int a = 0; a < NAA; a++) {
        int lo = g_base[a] + g_hist[a];
        int hi = g_base[a] + (snb[a] << 7);
        for (int i = lo + tid; i < hi; i += 256) g_perm[i] = -1;
    }
}

// ---------------------------------------------------------------------------
// Scatter: block-aggregated
// ---------------------------------------------------------------------------
__global__ void __launch_bounds__(256) scatter_kernel(const int* __restrict__ aa)
{
    __shared__ int sh_cnt[NAA];
    __shared__ int sh_base[NAA];
    const int tid = threadIdx.x;
    const int i   = blockIdx.x * 256 + tid;

    if (tid < NAA) sh_cnt[tid] = 0;
    __syncthreads();

    int a = aa[i];
    int rank = atomicAdd(&sh_cnt[a], 1);
    __syncthreads();

    if (tid < NAA && sh_cnt[tid] > 0)
        sh_base[tid] = atomicAdd(&g_cnt[tid], sh_cnt[tid]);
    __syncthreads();

    g_perm[g_base[a] + sh_base[a] + rank] = i;
}

__device__ __forceinline__ bool read_mask(const void* m, int mode, size_t i)
{
    if (mode == 0) return ((const int*)m)[i] != 0;
    if (mode == 1) return ((const float*)m)[i] != 0.0f;
    return ((const unsigned char*)m)[i] != 0;
}

// ---------------------------------------------------------------------------
// Frame construction -> packed half2 crd
// ---------------------------------------------------------------------------
__global__ void __launch_bounds__(128) frame_kernel(
    const float* __restrict__ pos14, const void* __restrict__ maskp)
{
    __shared__ float sp[128 * CRD];
    const int tid  = threadIdx.x;
    const int base = blockIdx.x * 128;

    const size_t gbase = (size_t)base * CRD;
    #pragma unroll 4
    for (int i = tid; i < 128 * CRD; i += 128) sp[i] = pos14[gbase + i];
    __syncthreads();

    const float* p = &sp[tid * CRD];
    const int t = base + tid;

    const float cx = p[3], cy = p[4], cz = p[5];
    float v1x = p[6] - cx, v1y = p[7] - cy, v1z = p[8] - cz;
    float n1 = sqrtf(v1x*v1x + v1y*v1y + v1z*v1z) + EPSF;
    float e1x = v1x / n1, e1y = v1y / n1, e1z = v1z / n1;

    float v2x = p[0] - cx, v2y = p[1] - cy, v2z = p[2] - cz;
    float d = e1x*v2x + e1y*v2y + e1z*v2z;
    float u2x = v2x - d*e1x, u2y = v2y - d*e1y, u2z = v2z - d*e1z;
    float n2 = sqrtf(u2x*u2x + u2y*u2y + u2z*u2z) + EPSF;
    float e2x = u2x / n2, e2y = u2y / n2, e2z = u2z / n2;

    float e3x = e1y*e2z - e1z*e2y;
    float e3y = e1z*e2x - e1x*e2z;
    float e3z = e1x*e2y - e1y*e2x;

    const int mode = g_mask_mode;
    float r[CRD];
    #pragma unroll
    for (int a = 0; a < 14; a++) {
        float qx = p[a*3+0] - cx, qy = p[a*3+1] - cy, qz = p[a*3+2] - cz;
        bool mk = read_mask(maskp, mode, (size_t)t * 14 + a);
        r[a*3+0] = mk ? (e1x*qx + e1y*qy + e1z*qz) : 0.0f;
        r[a*3+1] = mk ? (e2x*qx + e2y*qy + e2z*qz) : 0.0f;
        r[a*3+2] = mk ? (e3x*qx + e3y*qy + e3z*qz) : 0.0f;
    }
    __syncthreads();

    unsigned* spu = (unsigned*)sp;
    #pragma unroll
    for (int k2 = 0; k2 < 21; k2++)
        spu[tid * 21 + k2] = pack_h2(r[2*k2], r[2*k2+1]);
    __syncthreads();
    const size_t obase = (size_t)base * 21;
    #pragma unroll 4
    for (int i = tid; i < 128 * 21; i += 128) g_crdh[obase + i] = spu[i];
}

// ---------------------------------------------------------------------------
// table[aa][j] = embed[aa] @ w1[882:1394, j] + b1[j]   grid (8, 21) x 128
// ---------------------------------------------------------------------------
__global__ void __launch_bounds__(128) embproj_kernel(
    const float* __restrict__ embed, const float* __restrict__ w1,
    const float* __restrict__ b1)
{
    __shared__ float se[FEATD];
    const int a  = blockIdx.y;
    const int c0 = blockIdx.x * 128;
    const int tid = threadIdx.x;
    for (int i = tid; i < FEATD; i += 128) se[i] = embed[a * FEATD + i];
    __syncthreads();

    const int j = c0 + tid;
    float acc = b1[j];
    const float* wp = w1 + (size_t)(NAA * CRD) * H1D + j;
    #pragma unroll 8
    for (int f = 0; f < FEATD; f++)
        acc += se[f] * wp[(size_t)f * H1D];
    g_table[a * H1D + j] = acc;
}

// ---------------------------------------------------------------------------
// Tiled-transpose weight packing into [n][k2] half2 layout.
// ---------------------------------------------------------------------------
__global__ void __launch_bounds__(256) wpack_all_kernel(
    const float* __restrict__ w2, const float* __restrict__ w3,
    const float* __restrict__ w4)
{
    __shared__ float s[64][33];
    int b = blockIdx.x;
    const float* w; unsigned* out; int K, bloc;
    if (b < 256)      { w = w2; out = g_w2p; K = H1D;  bloc = b; }
    else if (b < 384) { w = w3; out = g_w3p; K = FEATD; bloc = b - 256; }
    else              { w = w4; out = g_w4p; K = FEATD; bloc = b - 384; }
    const int nTilesN = FEATD / 32;
    int tn = bloc % nTilesN, tk = bloc / nTilesN;
    int n0 = tn * 32, k0 = tk * 64;

    const int tx = threadIdx.x, ty = threadIdx.y;
    #pragma unroll
    for (int r = ty; r < 64; r += 8)
        s[r][tx] = w[(size_t)(k0 + r) * FEATD + n0 + tx];
    __syncthreads();

    const int K2 = K >> 1;
    #pragma unroll
    for (int i = ty; i < 32; i += 8)
        out[(size_t)(n0 + i) * K2 + (k0 >> 1) + tx] =
            pack_h2(s[2 * tx][i], s[2 * tx + 1][i]);
}

// ---------------------------------------------------------------------------
// Layer 1: aa-grouped fp16 mma GEMM (K=42 padded to 48).
// ---------------------------------------------------------------------------
#define L1_K2  24
#define L1_CS  28
#define L1_WS  136
#define L1_SMEM ((128 * L1_CS + L1_K2 * L1_WS) * 4 + 128 * 4 + 128 * 4)

__global__ void __launch_bounds__(256) layer1_gemm(const float* __restrict__ w1)
{
    extern __shared__ unsigned l1sm[];
    unsigned* s_crd = l1sm;
    unsigned* s_w   = l1sm + 128 * L1_CS;
    int*      s_tok = (int*)(l1sm + 128 * L1_CS + L1_K2 * L1_WS);
    float*    s_tab = (float*)(s_tok + 128);

    const int bm = blockIdx.y;
    const int a  = g_blk_aa[bm];
    if (a < 0) return;
    const int colbase = blockIdx.x * 128;

    const int tid  = threadIdx.x;
    const int wid  = tid >> 5;
    const int lane = tid & 31;
    const int gid  = lane >> 2;
    const int tig  = lane & 3;
    const int warpM = (wid >> 2) * 64;
    const int warpN = (wid & 3) * 32;

    for (int i = tid; i < 128 * L1_CS; i += 256) s_crd[i] = 0;
    if (tid < 128) {
        s_tok[tid] = g_perm[bm * 128 + tid];
        s_tab[tid] = g_table[a * H1D + colbase + tid];
    }
    __syncthreads();

    for (int i = tid; i < 128 * 21; i += 256) {
        int row = i / 21, k2 = i - row * 21;
        int t = s_tok[row];
        if (t >= 0) s_crd[row * L1_CS + k2] = g_crdh[(size_t)t * 21 + k2];
    }
    #pragma unroll
    for (int l = 0; l < 3; l++) {
        int s   = tid + l * 256;
        int kr2 = s >> 5;
        int nc  = s & 31;
        unsigned o0 = 0, o1 = 0, o2 = 0, o3 = 0;
        if (kr2 < 21) {
            const float* r0 = w1 + (size_t)(a * CRD + 2 * kr2) * H1D + colbase + nc * 4;
            float4 v0 = *(const float4*)(r0);
            float4 v1 = *(const float4*)(r0 + H1D);
            o0 = pack_h2(v0.x, v1.x); o1 = pack_h2(v0.y, v1.y);
            o2 = pack_h2(v0.z, v1.z); o3 = pack_h2(v0.w, v1.w);
        }
        unsigned* wp = &s_w[kr2 * L1_WS + nc * 4];
        wp[0] = o0; wp[1] = o1; wp[2] = o2; wp[3] = o3;
    }
    __syncthreads();

    float acc[4][4][4];
    #pragma unroll
    for (int i = 0; i < 4; i++)
        #pragma unroll
        for (int j = 0; j < 4; j++)
            #pragma unroll
            for (int c = 0; c < 4; c++) acc[i][j][c] = 0.0f;

    #pragma unroll
    for (int kb = 0; kb < L1_K2; kb += 8) {
        unsigned af[4][4], bf[4][2];
        #pragma unroll
        for (int mf = 0; mf < 4; mf++) {
            int r = warpM + mf * 16 + gid;
            af[mf][0] = s_crd[r * L1_CS + kb + tig];
            af[mf][1] = s_crd[(r + 8) * L1_CS + kb + tig];
            af[mf][2] = s_crd[r * L1_CS + kb + tig + 4];
            af[mf][3] = s_crd[(r + 8) * L1_CS + kb + tig + 4];
        }
        #pragma unroll
        for (int nf = 0; nf < 4; nf++) {
            int c = warpN + nf * 8 + gid;
            bf[nf][0] = s_w[(kb + tig) * L1_WS + c];
            bf[nf][1] = s_w[(kb + tig + 4) * L1_WS + c];
        }
        #pragma unroll
        for (int mf = 0; mf < 4; mf++)
            #pragma unroll
            for (int nf = 0; nf < 4; nf++)
                MMA16816(acc[mf][nf], af[mf], bf[nf][0], bf[nf][1]);
    }

    #pragma unroll
    for (int nf = 0; nf < 4; nf++) {
        int c = warpN + nf * 8 + 2 * tig;
        float bx = s_tab[c], by = s_tab[c + 1];
        #pragma unroll
        for (int mf = 0; mf < 4; mf++) {
            int r = warpM + mf * 16 + gid;
            int t0 = s_tok[r], t1 = s_tok[r + 8];
            if (t0 >= 0) {
                unsigned o = pack_h2(fmaxf(acc[mf][nf][0] + bx, 0.f),
                                     fmaxf(acc[mf][nf][1] + by, 0.f));
                *(unsigned*)(g_h1h + (size_t)t0 * H1D + colbase + c) = o;
            }
            if (t1 >= 0) {
                unsigned o = pack_h2(fmaxf(acc[mf][nf][2] + bx, 0.f),
                                     fmaxf(acc[mf][nf][3] + by, 0.f));
                *(unsigned*)(g_h1h + (size_t)t1 * H1D + colbase + c) = o;
            }
        }
    }
}

// ---------------------------------------------------------------------------
// Layer 2 GEMM (unchanged R12/R14 design): fp16 mma, 3-stage cp.async ring,
// both fragments via ldmatrix.  Tile 128x128x64. 2 CTA/SM.
// ---------------------------------------------------------------------------
#define GA_STRIDE 36
#define GW_STRIDE 36
#define GA_TILE  (128 * GA_STRIDE)
#define GW_TILE  (128 * GW_STRIDE)
#define NST      3
#define G_SMEM   ((NST * (GA_TILE + GW_TILE)) * 4)

__global__ void __launch_bounds__(256, 2) gemm_f16(
    const __half* __restrict__ A, const unsigned* __restrict__ Wp,
    const float* __restrict__ bias, void* __restrict__ Cout,
    int M, int K, int N, int relu, int out_half)
{
    extern __shared__ unsigned gsm[];
    unsigned* Ah = gsm;
    unsigned* Wh = gsm + NST * GA_TILE;

    const int tid  = threadIdx.x;
    const int wid  = tid >> 5;
    const int lane = tid & 31;
    const int gid  = lane >> 2;
    const int tig  = lane & 3;
    const int warpM = (wid >> 2) * 64;
    const int warpN = (wid & 3) * 32;
    const int row0 = blockIdx.y * 128;
    const int col0 = blockIdx.x * 128;
    const int K2   = K >> 1;

    uint32_t aDst0[4], wDst0[4];
    const __half* aSrc[4];
    const unsigned* wSrc[4];
    #pragma unroll
    for (int l = 0; l < 4; l++) {
        int s = tid + l * 256;
        int r = s >> 3, kq = s & 7;
        aSrc[l] = A + (size_t)(row0 + r) * K + kq * 8;
        wSrc[l] = Wp + (size_t)(col0 + r) * K2 + kq * 4;
        aDst0[l] = smem_u32(&Ah[r * GA_STRIDE + kq * 4]);
        wDst0[l] = smem_u32(&Wh[r * GW_STRIDE + kq * 4]);
    }

    uint32_t aFrag0[4];
    #pragma unroll
    for (int mf = 0; mf < 4; mf++) {
        int row = warpM + mf * 16 + ((lane >> 3) & 1) * 8 + (lane & 7);
        aFrag0[mf] = smem_u32(Ah) + (uint32_t)(row * GA_STRIDE * 4)
                   + (uint32_t)((lane >> 4) * 16);
    }
    uint32_t wFrag0[2];
    #pragma unroll
    for (int p = 0; p < 2; p++) {
        int rowN = warpN + p * 16 + ((lane >> 4) & 1) * 8 + (lane & 7);
        wFrag0[p] = smem_u32(Wh) + (uint32_t)(rowN * GW_STRIDE * 4)
                  + (uint32_t)(((lane >> 3) & 1) * 16);
    }

    #define STAGE(BUF, CH)                                                     \
        {                                                                      \
            _Pragma("unroll")                                                  \
            for (int l = 0; l < 4; l++)                                        \
                CP_ASYNC16(aDst0[l] + (BUF) * (GA_TILE * 4),                   \
                           aSrc[l] + (size_t)(CH) * 64);                       \
            _Pragma("unroll")                                                  \
            for (int l = 0; l < 4; l++)                                        \
                CP_ASYNC16(wDst0[l] + (BUF) * (GW_TILE * 4),                   \
                           wSrc[l] + (size_t)(CH) * 32);                       \
            CP_COMMIT();                                                       \
        }

    float acc[4][4][4];
    #pragma unroll
    for (int i = 0; i < 4; i++)
        #pragma unroll
        for (int j = 0; j < 4; j++)
            #pragma unroll
            for (int c = 0; c < 4; c++) acc[i][j][c] = 0.0f;

    const int nk = K >> 6;
    STAGE(0, 0);
    STAGE(1, 1);

    for (int ch = 0; ch < nk; ch++) {
        if (ch + 2 <= nk) { CP_WAIT(1); }
        else              { CP_WAIT(0); }
        __syncthreads();
        if (ch + 2 < nk) STAGE((ch + 2) % NST, ch + 2);

        const uint32_t bufA = (uint32_t)((ch % NST) * (GA_TILE * 4));
        const uint32_t bufW = (uint32_t)((ch % NST) * (GW_TILE * 4));
        #pragma unroll
        for (int kt = 0; kt < 4; kt++) {
            unsigned af[4][4], bf[4][2];
            #pragma unroll
            for (int mf = 0; mf < 4; mf++)
                LDSM_X4(af[mf][0], af[mf][1], af[mf][2], af[mf][3],
                        aFrag0[mf] + bufA + (uint32_t)(kt * 32));
            LDSM_X4(bf[0][0], bf[0][1], bf[1][0], bf[1][1],
                    wFrag0[0] + bufW + (uint32_t)(kt * 32));
            LDSM_X4(bf[2][0], bf[2][1], bf[3][0], bf[3][1],
                    wFrag0[1] + bufW + (uint32_t)(kt * 32));
            #pragma unroll
            for (int mf = 0; mf < 4; mf++)
                #pragma unroll
                for (int nf = 0; nf < 4; nf++)
                    MMA16816(acc[mf][nf], af[mf], bf[nf][0], bf[nf][1]);
        }
    }

    #pragma unroll
    for (int nf = 0; nf < 4; nf++) {
        int c = col0 + warpN + nf * 8 + 2 * tig;
        float bx = bias[c], by = bias[c + 1];
        #pragma unroll
        for (int mf = 0; mf < 4; mf++) {
            int r = row0 + warpM + mf * 16 + gid;
            float o0x = acc[mf][nf][0] + bx, o0y = acc[mf][nf][1] + by;
            float o1x = acc[mf][nf][2] + bx, o1y = acc[mf][nf][3] + by;
            if (relu) {
                o0x = fmaxf(o0x, 0.f); o0y = fmaxf(o0y, 0.f);
                o1x = fmaxf(o1x, 0.f); o1y = fmaxf(o1y, 0.f);
            }
            if (out_half) {
                __half* C = (__half*)Cout;
                *(unsigned*)(C + (size_t)r * N + c)       = pack_h2(o0x, o0y);
                *(unsigned*)(C + (size_t)(r + 8) * N + c) = pack_h2(o1x, o1y);
            } else {
                float* C = (float*)Cout;
                *(float2*)(C + (size_t)r * N + c)       = make_float2(o0x, o0y);
                *(float2*)(C + (size_t)(r + 8) * N + c) = make_float2(o1x, o1y);
            }
        }
    }
}

// ---------------------------------------------------------------------------
// Fused layers 3+4: out = (relu(h2@w3+b3)) @ w4 + b4 for one 128-row block.
// Phase A: 4 col-passes produce h3[128][512] fp16 into smem [128][260] uints.
// Phase B: 4 col-passes compute out, h3 A-frags via ldmatrix from smem.
// 256 thr, grid 512, 1 CTA/SM.  smem = 133120 + 73728 = 206848 B.
// ---------------------------------------------------------------------------
#define F_H3S   260                     // h3 row stride in uints
#define F_H3SZ  (128 * F_H3S)           // uints
#define F_TILE  (128 * 36)              // staging tile uints
#define F_SMEM  ((F_H3SZ + 4 * F_TILE) * 4)

__global__ void __launch_bounds__(256, 1) gemm_fused34(
    const __half* __restrict__ A, const unsigned* __restrict__ W3p,
    const float* __restrict__ b3, const unsigned* __restrict__ W4p,
    const float* __restrict__ b4, float* __restrict__ Out)
{
    extern __shared__ unsigned fsm[];
    unsigned* h3s = fsm;                        // [128][260]
    unsigned* stA = fsm + F_H3SZ;               // [2][128][36]  (A tiles)
    unsigned* stW = fsm + F_H3SZ + 2 * F_TILE;  // [2][128][36]  (W tiles)

    const int tid  = threadIdx.x;
    const int wid  = tid >> 5;
    const int lane = tid & 31;
    const int gid  = lane >> 2;
    const int tig  = lane & 3;
    const int warpM = (wid >> 2) * 64;
    const int warpN = (wid & 3) * 32;
    const int row0 = blockIdx.x * 128;

    // per-thread staging slots (shared by both phases)
    int slotR[4], slotKq[4];
    uint32_t aDst0[4], wDst0[4];
    #pragma unroll
    for (int l = 0; l < 4; l++) {
        int s = tid + l * 256;
        slotR[l] = s >> 3; slotKq[l] = s & 7;
        aDst0[l] = smem_u32(&stA[slotR[l] * 36 + slotKq[l] * 4]);
        wDst0[l] = smem_u32(&stW[slotR[l] * 36 + slotKq[l] * 4]);
    }

    // fragment bases
    uint32_t aFrag0[4];                         // for staged A tiles (stride 36)
    #pragma unroll
    for (int mf = 0; mf < 4; mf++) {
        int row = warpM + mf * 16 + ((lane >> 3) & 1) * 8 + (lane & 7);
        aFrag0[mf] = smem_u32(stA) + (uint32_t)(row * 36 * 4)
                   + (uint32_t)((lane >> 4) * 16);
    }
    uint32_t h3Frag[4];                         // for h3 smem (stride 260)
    #pragma unroll
    for (int mf = 0; mf < 4; mf++) {
        int row = warpM + mf * 16 + ((lane >> 3) & 1) * 8 + (lane & 7);
        h3Frag[mf] = smem_u32(h3s) + (uint32_t)(row * F_H3S * 4)
                   + (uint32_t)((lane >> 4) * 16);
    }
    uint32_t wFrag0[2];
    #pragma unroll
    for (int p = 0; p < 2; p++) {
        int rowN = warpN + p * 16 + ((lane >> 4) & 1) * 8 + (lane & 7);
        wFrag0[p] = smem_u32(stW) + (uint32_t)(rowN * 36 * 4)
                  + (uint32_t)(((lane >> 3) & 1) * 16);
    }

    float acc[4][4][4];

    #define FSTAGE_A(BUF, KC)                                                  \
        { _Pragma("unroll")                                                    \
          for (int l = 0; l < 4; l++)                                          \
              CP_ASYNC16(aDst0[l] + (BUF) * (F_TILE * 4),                      \
                  A + (size_t)(row0 + slotR[l]) * FEATD + (KC) * 64 + slotKq[l] * 8); }
    #define FSTAGE_W(BUF, KC, WPTR, C0)                                        \
        { _Pragma("unroll")                                                    \
          for (int l = 0; l < 4; l++)                                          \
              CP_ASYNC16(wDst0[l] + (BUF) * (F_TILE * 4),                      \
                  (WPTR) + (size_t)((C0) + slotR[l]) * 256 + (KC) * 32 + slotKq[l] * 4); }

    // ================= Phase A: h3 = relu(h2 @ w3 + b3) ====================
    for (int c = 0; c < 4; c++) {
        const int c0 = c * 128;
        #pragma unroll
        for (int i = 0; i < 4; i++)
            #pragma unroll
            for (int j = 0; j < 4; j++)
                #pragma unroll
                for (int q = 0; q < 4; q++) acc[i][j][q] = 0.0f;

        FSTAGE_A(0, 0); FSTAGE_W(0, 0, W3p, c0); CP_COMMIT();
        for (int kc = 0; kc < 8; kc++) {
            const int buf = kc & 1;
            if (kc + 1 < 8) {
                FSTAGE_A(1 - buf, kc + 1); FSTAGE_W(1 - buf, kc + 1, W3p, c0);
                CP_COMMIT(); CP_WAIT(1);
            } else CP_WAIT(0);
            __syncthreads();

            const uint32_t oA = (uint32_t)(buf * (F_TILE * 4));
            #pragma unroll
            for (int kt = 0; kt < 4; kt++) {
                unsigned af[4][4], bf[4][2];
                #pragma unroll
                for (int mf = 0; mf < 4; mf++)
                    LDSM_X4(af[mf][0], af[mf][1], af[mf][2], af[mf][3],
                            aFrag0[mf] + oA + (uint32_t)(kt * 32));
                LDSM_X4(bf[0][0], bf[0][1], bf[1][0], bf[1][1],
                        wFrag0[0] + oA + (uint32_t)(kt * 32));
                LDSM_X4(bf[2][0], bf[2][1], bf[3][0], bf[3][1],
                        wFrag0[1] + oA + (uint32_t)(kt * 32));
                #pragma unroll
                for (int mf = 0; mf < 4; mf++)
                    #pragma unroll
                    for (int nf = 0; nf < 4; nf++)
                        MMA16816(acc[mf][nf], af[mf], bf[nf][0], bf[nf][1]);
            }
            __syncthreads();
        }

        // epilogue: relu + b3, pack into h3 smem at k2 = (c0 + col)/2
        #pragma unroll
        for (int nf = 0; nf < 4; nf++) {
            int col = warpN + nf * 8 + 2 * tig;
            float bx = b3[c0 + col], by = b3[c0 + col + 1];
            int k2 = (c0 + col) >> 1;
            #pragma unroll
            for (int mf = 0; mf < 4; mf++) {
                int r = warpM + mf * 16 + gid;
                h3s[r * F_H3S + k2] =
                    pack_h2(fmaxf(acc[mf][nf][0] + bx, 0.f),
                            fmaxf(acc[mf][nf][1] + by, 0.f));
                h3s[(r + 8) * F_H3S + k2] =
                    pack_h2(fmaxf(acc[mf][nf][2] + bx, 0.f),
                            fmaxf(acc[mf][nf][3] + by, 0.f));
            }
        }
        __syncthreads();
    }

    // ================= Phase B: out = h3 @ w4 + b4 =========================
    for (int c = 0; c < 4; c++) {
        const int c0 = c * 128;
        #pragma unroll
        for (int i = 0; i < 4; i++)
            #pragma unroll
            for (int j = 0; j < 4; j++)
                #pragma unroll
                for (int q = 0; q < 4; q++) acc[i][j][q] = 0.0f;

        FSTAGE_W(0, 0, W4p, c0); CP_COMMIT();
        for (int kc = 0; kc < 8; kc++) {
            const int buf = kc & 1;
            if (kc + 1 < 8) {
                FSTAGE_W(1 - buf, kc + 1, W4p, c0);
                CP_COMMIT(); CP_WAIT(1);
            } else CP_WAIT(0);
            __syncthreads();

            const uint32_t oW = (uint32_t)(buf * (F_TILE * 4));
            const uint32_t oH = (uint32_t)(kc * 128);   // 32 uints = 128 B per k-chunk
            #pragma unroll
            for (int kt = 0; kt < 4; kt++) {
                unsigned af[4][4], bf[4][2];
                #pragma unroll
                for (int mf = 0; mf < 4; mf++)
                    LDSM_X4(af[mf][0], af[mf][1], af[mf][2], af[mf][3],
                            h3Frag[mf] + oH + (uint32_t)(kt * 32));
                LDSM_X4(bf[0][0], bf[0][1], bf[1][0], bf[1][1],
                        wFrag0[0] + oW + (uint32_t)(kt * 32));
                LDSM_X4(bf[2][0], bf[2][1], bf[3][0], bf[3][1],
                        wFrag0[1] + oW + (uint32_t)(kt * 32));
                #pragma unroll
                for (int mf = 0; mf < 4; mf++)
                    #pragma unroll
                    for (int nf = 0; nf < 4; nf++)
                        MMA16816(acc[mf][nf], af[mf], bf[nf][0], bf[nf][1]);
            }
            __syncthreads();
        }

        // epilogue: + b4, fp32 out
        #pragma unroll
        for (int nf = 0; nf < 4; nf++) {
            int col = c0 + warpN + nf * 8 + 2 * tig;
            float bx = b4[col], by = b4[col + 1];
            #pragma unroll
            for (int mf = 0; mf < 4; mf++) {
                int r = row0 + warpM + mf * 16 + gid;
                *(float2*)(Out + (size_t)r * FEATD + col) =
                    make_float2(acc[mf][nf][0] + bx, acc[mf][nf][1] + by);
                *(float2*)(Out + (size_t)(r + 8) * FEATD + col) =
                    make_float2(acc[mf][nf][2] + bx, acc[mf][nf][3] + by);
            }
        }
    }
}

extern "C" void kernel_launch(void* const* d_in, const int* in_sizes, int n_in,
                              void* d_out, int out_size)
{
    const int*   aa    = (const int*)  d_in[0];
    const float* pos14 = (const float*)d_in[1];
    const void*  amask =               d_in[2];
    const float* embed = (const float*)d_in[3];
    const float* w1    = (const float*)d_in[4];
    const float* b1    = (const float*)d_in[5];
    const float* w2    = (const float*)d_in[6];
    const float* b2    = (const float*)d_in[7];
    const float* w3    = (const float*)d_in[8];
    const float* b3    = (const float*)d_in[9];
    const float* w4    = (const float*)d_in[10];
    const float* b4    = (const float*)d_in[11];

    __half *p_h1h, *p_h2h;
    cudaGetSymbolAddress((void**)&p_h1h, g_h1h);
    cudaGetSymbolAddress((void**)&p_h2h, g_h2h);
    unsigned *p_w2p, *p_w3p, *p_w4p;
    cudaGetSymbolAddress((void**)&p_w2p, g_w2p);
    cudaGetSymbolAddress((void**)&p_w3p, g_w3p);
    cudaGetSymbolAddress((void**)&p_w4p, g_w4p);

    cudaFuncSetAttribute(layer1_gemm, cudaFuncAttributeMaxDynamicSharedMemorySize,
                         L1_SMEM);
    cudaFuncSetAttribute(gemm_f16, cudaFuncAttributeMaxDynamicSharedMemorySize,
                         G_SMEM);
    cudaFuncSetAttribute(gemm_fused34, cudaFuncAttributeMaxDynamicSharedMemorySize,
                         F_SMEM);

    // prologue
    prep_kernel<<<64, 256>>>((const unsigned int*)amask, aa);
    scan_kernel<<<1, 256>>>();
    scatter_kernel<<<M_TOK / 256, 256>>>(aa);
    frame_kernel<<<M_TOK / 128, 128>>>(pos14, amask);
    embproj_kernel<<<dim3(H1D / 128, NAA), 128>>>(embed, w1, b1);
    wpack_all_kernel<<<512, dim3(32, 8)>>>(w2, w3, w4);

    // layer 1 (grouped fp16 GEMM)
    {
        dim3 g(H1D / 128, MAXBLK);
        layer1_gemm<<<g, 256, L1_SMEM>>>(w1);
    }

    // layer 2, then fused layers 3+4
    {
        dim3 blk(256);
        dim3 g2(FEATD / 128, M_TOK / 128);
        gemm_f16<<<g2, blk, G_SMEM>>>(p_h1h, p_w2p, b2, p_h2h, M_TOK, H1D, FEATD, 1, 1);
        gemm_fused34<<<M_TOK / 128, blk, F_SMEM>>>(p_h2h, p_w3p, b3, p_w4p, b4,
                                                   (float*)d_out);
    }
}

// round 16
// speedup vs baseline: 1.0931x; 1.0931x over previous
#include <cuda_runtime.h>
#include <cuda_fp16.h>
#include <cstdint>

// Problem constants (fixed shapes per reference)
#define M_TOK   65536          // N*L = 16*4096
#define FEATD   512
#define H1D     1024
#define NAA     21
#define CRD     42             // 14*3
#define EPSF    1e-6f
#define MAXBLK  533            // 65536/128 + 21 (padded 128-token groups)

// -------- static device scratch (no runtime allocation allowed) ----------
__device__ unsigned g_crdh[(size_t)M_TOK * 21];        // packed half2 crd
__device__ float    g_table[NAA * H1D];                // embed[aa]@w1[882:]+b1
__device__ __half   g_h1h[(size_t)M_TOK * H1D];        // 128 MB  (fp16 h1)
__device__ __half   g_h2h[(size_t)M_TOK * FEATD];      // 64 MB
__device__ __half   g_h3h[(size_t)M_TOK * FEATD];      // 64 MB
// W packed as [n][k2] (K-major per column, half2 along k)
__device__ unsigned g_w2p[(size_t)FEATD * (H1D/2)];    // 262144 packed half2
__device__ unsigned g_w3p[(size_t)FEATD * (FEATD/2)];  // 131072
__device__ unsigned g_w4p[(size_t)FEATD * (FEATD/2)];  // 131072
__device__ int      g_mask_mode;
// sorting scratch
__device__ int      g_histp[64][NAA];
__device__ unsigned g_mflag[64];
__device__ int      g_hist[NAA];
__device__ int      g_cnt[NAA];
__device__ int      g_base[NAA];
__device__ int      g_blk_aa[MAXBLK];
__device__ int      g_perm[MAXBLK * 128];

// ---------------------------------------------------------------------------
__device__ __forceinline__ uint32_t smem_u32(const void* p)
{
    uint32_t a;
    asm("{ .reg .u64 t; cvta.to.shared.u64 t, %1; cvt.u32.u64 %0, t; }"
        : "=r"(a) : "l"(p));
    return a;
}

#define CP_ASYNC16(dst, src) \
    asm volatile("cp.async.cg.shared.global [%0], [%1], 16;" \
                 :: "r"(dst), "l"(src) : "memory")
#define CP_COMMIT()  asm volatile("cp.async.commit_group;" ::: "memory")
#define CP_WAIT(n)   asm volatile("cp.async.wait_group %0;" :: "n"(n) : "memory")

#define LDSM_X4(R0, R1, R2, R3, ADDR) \
    asm volatile("ldmatrix.sync.aligned.m8n8.x4.shared.b16 {%0,%1,%2,%3}, [%4];" \
        : "=r"(R0), "=r"(R1), "=r"(R2), "=r"(R3) : "r"(ADDR))

#define MMA16816(ACC, AF, B0, B1)                                              \
    asm volatile(                                                              \
        "mma.sync.aligned.m16n8k16.row.col.f32.f16.f16.f32 "                   \
        "{%0,%1,%2,%3}, {%4,%5,%6,%7}, {%8,%9}, {%0,%1,%2,%3};"                \
        : "+f"((ACC)[0]), "+f"((ACC)[1]), "+f"((ACC)[2]), "+f"((ACC)[3])       \
        : "r"((AF)[0]), "r"((AF)[1]), "r"((AF)[2]), "r"((AF)[3]),              \
          "r"(B0), "r"(B1))

__device__ __forceinline__ unsigned pack_h2(float a, float b)
{
    __half2 h = __floats2half2_rn(a, b);
    return *(unsigned*)&h;
}

// ---------------------------------------------------------------------------
// Fused mask-sniff + per-block histogram. 64 blocks x 256.
// ---------------------------------------------------------------------------
__global__ void __launch_bounds__(256) prep_kernel(
    const unsigned int* __restrict__ maskw, const int* __restrict__ aa)
{
    __shared__ int h[NAA];
    __shared__ unsigned fl;
    const int tid = threadIdx.x;
    const int b   = blockIdx.x;
    if (tid < NAA) h[tid] = 0;
    if (tid == 0)  fl = 0;
    __syncthreads();

    int base = b * 1024;
    for (int j = tid; j < 1024; j += 256) atomicAdd(&h[aa[base + j]], 1);
    if (tid < 64) {
        unsigned v = maskw[b * 64 + tid];
        if (v == 0x3F800000u) atomicOr(&fl, 1u);
        else if (v > 1u)      atomicOr(&fl, 2u);
    }
    __syncthreads();
    if (tid < NAA) g_histp[b][tid] = h[tid];
    if (tid == 0)  g_mflag[b] = fl;
}

// ---------------------------------------------------------------------------
// Scan: reduce partials, resolve mask mode, bases, blk->aa map, pad perm.
// ---------------------------------------------------------------------------
__global__ void __launch_bounds__(256) scan_kernel()
{
    __shared__ int sbase[NAA], snb[NAA];
    const int tid = threadIdx.x;

    for (int a = tid; a < NAA; a += 256) {
        int s = 0;
        #pragma unroll 8
        for (int b = 0; b < 64; b++) s += g_histp[b][a];
        g_hist[a] = s;
        g_cnt[a]  = 0;
    }
    if (tid == 0) {
        unsigned f = 0;
        for (int b = 0; b < 64; b++) f |= g_mflag[b];
        g_mask_mode = (f & 1u) ? 1 : ((f & 2u) ? 2 : 0);
    }
    __syncthreads();

    if (tid == 0) {
        int cur = 0;
        for (int a = 0; a < NAA; a++) {
            sbase[a] = cur >> 7;
            int nb = (g_hist[a] + 127) >> 7;
            snb[a] = nb;
            g_base[a] = cur;
            cur += nb << 7;
        }
    }
    __syncthreads();

    for (int b = tid; b < MAXBLK; b += 256) {
        int av = -1;
        #pragma unroll
        for (int a = 0; a < NAA; a++)
            if (b >= sbase[a] && b < sbase[a] + snb[a]) av = a;
        g_blk_aa[b] = av;
    }
    for (int a = 0; a < NAA; a++) {
        int lo = g_base[a] + g_hist[a];
        int hi = g_base[a] + (snb[a] << 7);
        for (int i = lo + tid; i < hi; i += 256) g_perm[i] = -1;
    }
}

__device__ __forceinline__ bool read_mask(const void* m, int mode, size_t i)
{
    if (mode == 0) return ((const int*)m)[i] != 0;
    if (mode == 1) return ((const float*)m)[i] != 0.0f;
    return ((const unsigned char*)m)[i] != 0;
}

// ---------------------------------------------------------------------------
// Frame construction -> packed half2 crd, PLUS fused block-aggregated scatter.
// 512 blocks x 128 threads (one token per thread).
// ---------------------------------------------------------------------------
__global__ void __launch_bounds__(128) frame_kernel(
    const float* __restrict__ pos14, const void* __restrict__ maskp,
    const int* __restrict__ aa)
{
    __shared__ float sp[128 * CRD];
    __shared__ int sh_cnt[NAA];
    __shared__ int sh_base[NAA];
    const int tid  = threadIdx.x;
    const int base = blockIdx.x * 128;

    if (tid < NAA) sh_cnt[tid] = 0;

    const size_t gbase = (size_t)base * CRD;
    #pragma unroll 4
    for (int i = tid; i < 128 * CRD; i += 128) sp[i] = pos14[gbase + i];
    __syncthreads();

    const float* p = &sp[tid * CRD];
    const int t = base + tid;

    const float cx = p[3], cy = p[4], cz = p[5];
    float v1x = p[6] - cx, v1y = p[7] - cy, v1z = p[8] - cz;
    float n1 = sqrtf(v1x*v1x + v1y*v1y + v1z*v1z) + EPSF;
    float e1x = v1x / n1, e1y = v1y / n1, e1z = v1z / n1;

    float v2x = p[0] - cx, v2y = p[1] - cy, v2z = p[2] - cz;
    float d = e1x*v2x + e1y*v2y + e1z*v2z;
    float u2x = v2x - d*e1x, u2y = v2y - d*e1y, u2z = v2z - d*e1z;
    float n2 = sqrtf(u2x*u2x + u2y*u2y + u2z*u2z) + EPSF;
    float e2x = u2x / n2, e2y = u2y / n2, e2z = u2z / n2;

    float e3x = e1y*e2z - e1z*e2y;
    float e3y = e1z*e2x - e1x*e2z;
    float e3z = e1x*e2y - e1y*e2x;

    const int mode = g_mask_mode;
    float r[CRD];
    #pragma unroll
    for (int a = 0; a < 14; a++) {
        float qx = p[a*3+0] - cx, qy = p[a*3+1] - cy, qz = p[a*3+2] - cz;
        bool mk = read_mask(maskp, mode, (size_t)t * 14 + a);
        r[a*3+0] = mk ? (e1x*qx + e1y*qy + e1z*qz) : 0.0f;
        r[a*3+1] = mk ? (e2x*qx + e2y*qy + e2z*qz) : 0.0f;
        r[a*3+2] = mk ? (e3x*qx + e3y*qy + e3z*qz) : 0.0f;
    }
    __syncthreads();

    unsigned* spu = (unsigned*)sp;
    #pragma unroll
    for (int k2 = 0; k2 < 21; k2++)
        spu[tid * 21 + k2] = pack_h2(r[2*k2], r[2*k2+1]);
    __syncthreads();
    const size_t obase = (size_t)base * 21;
    #pragma unroll 4
    for (int i = tid; i < 128 * 21; i += 128) g_crdh[obase + i] = spu[i];

    // ---- fused scatter (block-aggregated ranking) ----
    int a = aa[t];
    int rank = atomicAdd(&sh_cnt[a], 1);
    __syncthreads();
    if (tid < NAA && sh_cnt[tid] > 0)
        sh_base[tid] = atomicAdd(&g_cnt[tid], sh_cnt[tid]);
    __syncthreads();
    g_perm[g_base[a] + sh_base[a] + rank] = t;
}

// ---------------------------------------------------------------------------
// table[aa][j] = embed[aa] @ w1[882:1394, j] + b1[j]   grid (8, 21) x 128
// ---------------------------------------------------------------------------
__global__ void __launch_bounds__(128) embproj_kernel(
    const float* __restrict__ embed, const float* __restrict__ w1,
    const float* __restrict__ b1)
{
    __shared__ float se[FEATD];
    const int a  = blockIdx.y;
    const int c0 = blockIdx.x * 128;
    const int tid = threadIdx.x;
    for (int i = tid; i < FEATD; i += 128) se[i] = embed[a * FEATD + i];
    __syncthreads();

    const int j = c0 + tid;
    float acc = b1[j];
    const float* wp = w1 + (size_t)(NAA * CRD) * H1D + j;
    #pragma unroll 8
    for (int f = 0; f < FEATD; f++)
        acc += se[f] * wp[(size_t)f * H1D];
    g_table[a * H1D + j] = acc;
}

// ---------------------------------------------------------------------------
// Tiled-transpose weight packing into [n][k2] half2 layout.
// ---------------------------------------------------------------------------
__global__ void __launch_bounds__(256) wpack_all_kernel(
    const float* __restrict__ w2, const float* __restrict__ w3,
    const float* __restrict__ w4)
{
    __shared__ float s[64][33];
    int b = blockIdx.x;
    const float* w; unsigned* out; int K, bloc;
    if (b < 256)      { w = w2; out = g_w2p; K = H1D;  bloc = b; }
    else if (b < 384) { w = w3; out = g_w3p; K = FEATD; bloc = b - 256; }
    else              { w = w4; out = g_w4p; K = FEATD; bloc = b - 384; }
    const int nTilesN = FEATD / 32;
    int tn = bloc % nTilesN, tk = bloc / nTilesN;
    int n0 = tn * 32, k0 = tk * 64;

    const int tx = threadIdx.x, ty = threadIdx.y;
    #pragma unroll
    for (int r = ty; r < 64; r += 8)
        s[r][tx] = w[(size_t)(k0 + r) * FEATD + n0 + tx];
    __syncthreads();

    const int K2 = K >> 1;
    #pragma unroll
    for (int i = ty; i < 32; i += 8)
        out[(size_t)(n0 + i) * K2 + (k0 >> 1) + tx] =
            pack_h2(s[2 * tx][i], s[2 * tx + 1][i]);
}

// ---------------------------------------------------------------------------
// Layer 1: aa-grouped fp16 mma GEMM (K=42 padded to 48).
// ---------------------------------------------------------------------------
#define L1_K2  24
#define L1_CS  28
#define L1_WS  136
#define L1_SMEM ((128 * L1_CS + L1_K2 * L1_WS) * 4 + 128 * 4 + 128 * 4)

__global__ void __launch_bounds__(256) layer1_gemm(const float* __restrict__ w1)
{
    extern __shared__ unsigned l1sm[];
    unsigned* s_crd = l1sm;
    unsigned* s_w   = l1sm + 128 * L1_CS;
    int*      s_tok = (int*)(l1sm + 128 * L1_CS + L1_K2 * L1_WS);
    float*    s_tab = (float*)(s_tok + 128);

    const int bm = blockIdx.y;
    const int a  = g_blk_aa[bm];
    if (a < 0) return;
    const int colbase = blockIdx.x * 128;

    const int tid  = threadIdx.x;
    const int wid  = tid >> 5;
    const int lane = tid & 31;
    const int gid  = lane >> 2;
    const int tig  = lane & 3;
    const int warpM = (wid >> 2) * 64;
    const int warpN = (wid & 3) * 32;

    for (int i = tid; i < 128 * L1_CS; i += 256) s_crd[i] = 0;
    if (tid < 128) {
        s_tok[tid] = g_perm[bm * 128 + tid];
        s_tab[tid] = g_table[a * H1D + colbase + tid];
    }
    __syncthreads();

    for (int i = tid; i < 128 * 21; i += 256) {
        int row = i / 21, k2 = i - row * 21;
        int t = s_tok[row];
        if (t >= 0) s_crd[row * L1_CS + k2] = g_crdh[(size_t)t * 21 + k2];
    }
    #pragma unroll
    for (int l = 0; l < 3; l++) {
        int s   = tid + l * 256;
        int kr2 = s >> 5;
        int nc  = s & 31;
        unsigned o0 = 0, o1 = 0, o2 = 0, o3 = 0;
        if (kr2 < 21) {
            const float* r0 = w1 + (size_t)(a * CRD + 2 * kr2) * H1D + colbase + nc * 4;
            float4 v0 = *(const float4*)(r0);
            float4 v1 = *(const float4*)(r0 + H1D);
            o0 = pack_h2(v0.x, v1.x); o1 = pack_h2(v0.y, v1.y);
            o2 = pack_h2(v0.z, v1.z); o3 = pack_h2(v0.w, v1.w);
        }
        unsigned* wp = &s_w[kr2 * L1_WS + nc * 4];
        wp[0] = o0; wp[1] = o1; wp[2] = o2; wp[3] = o3;
    }
    __syncthreads();

    float acc[4][4][4];
    #pragma unroll
    for (int i = 0; i < 4; i++)
        #pragma unroll
        for (int j = 0; j < 4; j++)
            #pragma unroll
            for (int c = 0; c < 4; c++) acc[i][j][c] = 0.0f;

    #pragma unroll
    for (int kb = 0; kb < L1_K2; kb += 8) {
        unsigned af[4][4], bf[4][2];
        #pragma unroll
        for (int mf = 0; mf < 4; mf++) {
            int r = warpM + mf * 16 + gid;
            af[mf][0] = s_crd[r * L1_CS + kb + tig];
            af[mf][1] = s_crd[(r + 8) * L1_CS + kb + tig];
            af[mf][2] = s_crd[r * L1_CS + kb + tig + 4];
            af[mf][3] = s_crd[(r + 8) * L1_CS + kb + tig + 4];
        }
        #pragma unroll
        for (int nf = 0; nf < 4; nf++) {
            int c = warpN + nf * 8 + gid;
            bf[nf][0] = s_w[(kb + tig) * L1_WS + c];
            bf[nf][1] = s_w[(kb + tig + 4) * L1_WS + c];
        }
        #pragma unroll
        for (int mf = 0; mf < 4; mf++)
            #pragma unroll
            for (int nf = 0; nf < 4; nf++)
                MMA16816(acc[mf][nf], af[mf], bf[nf][0], bf[nf][1]);
    }

    #pragma unroll
    for (int nf = 0; nf < 4; nf++) {
        int c = warpN + nf * 8 + 2 * tig;
        float bx = s_tab[c], by = s_tab[c + 1];
        #pragma unroll
        for (int mf = 0; mf < 4; mf++) {
            int r = warpM + mf * 16 + gid;
            int t0 = s_tok[r], t1 = s_tok[r + 8];
            if (t0 >= 0) {
                unsigned o = pack_h2(fmaxf(acc[mf][nf][0] + bx, 0.f),
                                     fmaxf(acc[mf][nf][1] + by, 0.f));
                *(unsigned*)(g_h1h + (size_t)t0 * H1D + colbase + c) = o;
            }
            if (t1 >= 0) {
                unsigned o = pack_h2(fmaxf(acc[mf][nf][2] + bx, 0.f),
                                     fmaxf(acc[mf][nf][3] + by, 0.f));
                *(unsigned*)(g_h1h + (size_t)t1 * H1D + colbase + c) = o;
            }
        }
    }
}

// ---------------------------------------------------------------------------
// Dense GEMM: fp16 mma, 3-stage cp.async ring, one barrier per 64-k chunk,
// both fragments via ldmatrix.  Tile 128x128x64. 2 CTA/SM.
// ---------------------------------------------------------------------------
#define GA_STRIDE 36
#define GW_STRIDE 36
#define GA_TILE  (128 * GA_STRIDE)
#define GW_TILE  (128 * GW_STRIDE)
#define NST      3
#define G_SMEM   ((NST * (GA_TILE + GW_TILE)) * 4)

__global__ void __launch_bounds__(256, 2) gemm_f16(
    const __half* __restrict__ A, const unsigned* __restrict__ Wp,
    const float* __restrict__ bias, void* __restrict__ Cout,
    int M, int K, int N, int relu, int out_half)
{
    extern __shared__ unsigned gsm[];
    unsigned* Ah = gsm;
    unsigned* Wh = gsm + NST * GA_TILE;

    const int tid  = threadIdx.x;
    const int wid  = tid >> 5;
    const int lane = tid & 31;
    const int gid  = lane >> 2;
    const int tig  = lane & 3;
    const int warpM = (wid >> 2) * 64;
    const int warpN = (wid & 3) * 32;
    const int row0 = blockIdx.y * 128;
    const int col0 = blockIdx.x * 128;
    const int K2   = K >> 1;

    uint32_t aDst0[4], wDst0[4];
    const __half* aSrc[4];
    const unsigned* wSrc[4];
    #pragma unroll
    for (int l = 0; l < 4; l++) {
        int s = tid + l * 256;
        int r = s >> 3, kq = s & 7;
        aSrc[l] = A + (size_t)(row0 + r) * K + kq * 8;
        wSrc[l] = Wp + (size_t)(col0 + r) * K2 + kq * 4;
        aDst0[l] = smem_u32(&Ah[r * GA_STRIDE + kq * 4]);
        wDst0[l] = smem_u32(&Wh[r * GW_STRIDE + kq * 4]);
    }

    uint32_t aFrag0[4];
    #pragma unroll
    for (int mf = 0; mf < 4; mf++) {
        int row = warpM + mf * 16 + ((lane >> 3) & 1) * 8 + (lane & 7);
        aFrag0[mf] = smem_u32(Ah) + (uint32_t)(row * GA_STRIDE * 4)
                   + (uint32_t)((lane >> 4) * 16);
    }
    uint32_t wFrag0[2];
    #pragma unroll
    for (int p = 0; p < 2; p++) {
        int rowN = warpN + p * 16 + ((lane >> 4) & 1) * 8 + (lane & 7);
        wFrag0[p] = smem_u32(Wh) + (uint32_t)(rowN * GW_STRIDE * 4)
                  + (uint32_t)(((lane >> 3) & 1) * 16);
    }

    #define STAGE(BUF, CH)                                                     \
        {                                                                      \
            _Pragma("unroll")                                                  \
            for (int l = 0; l < 4; l++)                                        \
                CP_ASYNC16(aDst0[l] + (BUF) * (GA_TILE * 4),                   \
                           aSrc[l] + (size_t)(CH) * 64);                       \
            _Pragma("unroll")                                                  \
            for (int l = 0; l < 4; l++)                                        \
                CP_ASYNC16(wDst0[l] + (BUF) * (GW_TILE * 4),                   \
                           wSrc[l] + (size_t)(CH) * 32);                       \
            CP_COMMIT();                                                       \
        }

    float acc[4][4][4];
    #pragma unroll
    for (int i = 0; i < 4; i++)
        #pragma unroll
        for (int j = 0; j < 4; j++)
            #pragma unroll
            for (int c = 0; c < 4; c++) acc[i][j][c] = 0.0f;

    const int nk = K >> 6;
    STAGE(0, 0);
    STAGE(1, 1);

    for (int ch = 0; ch < nk; ch++) {
        if (ch + 2 <= nk) { CP_WAIT(1); }
        else              { CP_WAIT(0); }
        __syncthreads();
        if (ch + 2 < nk) STAGE((ch + 2) % NST, ch + 2);

        const uint32_t bufA = (uint32_t)((ch % NST) * (GA_TILE * 4));
        const uint32_t bufW = (uint32_t)((ch % NST) * (GW_TILE * 4));
        #pragma unroll
        for (int kt = 0; kt < 4; kt++) {
            unsigned af[4][4], bf[4][2];
            #pragma unroll
            for (int mf = 0; mf < 4; mf++)
                LDSM_X4(af[mf][0], af[mf][1], af[mf][2], af[mf][3],
                        aFrag0[mf] + bufA + (uint32_t)(kt * 32));
            LDSM_X4(bf[0][0], bf[0][1], bf[1][0], bf[1][1],
                    wFrag0[0] + bufW + (uint32_t)(kt * 32));
            LDSM_X4(bf[2][0], bf[2][1], bf[3][0], bf[3][1],
                    wFrag0[1] + bufW + (uint32_t)(kt * 32));
            #pragma unroll
            for (int mf = 0; mf < 4; mf++)
                #pragma unroll
                for (int nf = 0; nf < 4; nf++)
                    MMA16816(acc[mf][nf], af[mf], bf[nf][0], bf[nf][1]);
        }
    }

    #pragma unroll
    for (int nf = 0; nf < 4; nf++) {
        int c = col0 + warpN + nf * 8 + 2 * tig;
        float bx = bias[c], by = bias[c + 1];
        #pragma unroll
        for (int mf = 0; mf < 4; mf++) {
            int r = row0 + warpM + mf * 16 + gid;
            float o0x = acc[mf][nf][0] + bx, o0y = acc[mf][nf][1] + by;
            float o1x = acc[mf][nf][2] + bx, o1y = acc[mf][nf][3] + by;
            if (relu) {
                o0x = fmaxf(o0x, 0.f); o0y = fmaxf(o0y, 0.f);
                o1x = fmaxf(o1x, 0.f); o1y = fmaxf(o1y, 0.f);
            }
            if (out_half) {
                __half* C = (__half*)Cout;
                *(unsigned*)(C + (size_t)r * N + c)       = pack_h2(o0x, o0y);
                *(unsigned*)(C + (size_t)(r + 8) * N + c) = pack_h2(o1x, o1y);
            } else {
                float* C = (float*)Cout;
                *(float2*)(C + (size_t)r * N + c)       = make_float2(o0x, o0y);
                *(float2*)(C + (size_t)(r + 8) * N + c) = make_float2(o1x, o1y);
            }
        }
    }
}

extern "C" void kernel_launch(void* const* d_in, const int* in_sizes, int n_in,
                              void* d_out, int out_size)
{
    const int*   aa    = (const int*)  d_in[0];
    const float* pos14 = (const float*)d_in[1];
    const void*  amask =               d_in[2];
    const float* embed = (const float*)d_in[3];
    const float* w1    = (const float*)d_in[4];
    const float* b1    = (const float*)d_in[5];
    const float* w2    = (const float*)d_in[6];
    const float* b2    = (const float*)d_in[7];
    const float* w3    = (const float*)d_in[8];
    const float* b3    = (const float*)d_in[9];
    const float* w4    = (const float*)d_in[10];
    const float* b4    = (const float*)d_in[11];

    __half *p_h1h, *p_h2h, *p_h3h;
    cudaGetSymbolAddress((void**)&p_h1h, g_h1h);
    cudaGetSymbolAddress((void**)&p_h2h, g_h2h);
    cudaGetSymbolAddress((void**)&p_h3h, g_h3h);
    unsigned *p_w2p, *p_w3p, *p_w4p;
    cudaGetSymbolAddress((void**)&p_w2p, g_w2p);
    cudaGetSymbolAddress((void**)&p_w3p, g_w3p);
    cudaGetSymbolAddress((void**)&p_w4p, g_w4p);

    cudaFuncSetAttribute(layer1_gemm, cudaFuncAttributeMaxDynamicSharedMemorySize,
                         L1_SMEM);
    cudaFuncSetAttribute(gemm_f16, cudaFuncAttributeMaxDynamicSharedMemorySize,
                         G_SMEM);

    // prologue: sniff+hist, scan, then frame(+fused scatter), embproj, wpack
    prep_kernel<<<64, 256>>>((const unsigned int*)amask, aa);
    scan_kernel<<<1, 256>>>();
    frame_kernel<<<M_TOK / 128, 128>>>(pos14, amask, aa);
    embproj_kernel<<<dim3(H1D / 128, NAA), 128>>>(embed, w1, b1);
    wpack_all_kernel<<<512, dim3(32, 8)>>>(w2, w3, w4);

    // layer 1 (grouped fp16 GEMM)
    {
        dim3 g(H1D / 128, MAXBLK);
        layer1_gemm<<<g, 256, L1_SMEM>>>(w1);
    }

    // dense MLP (fp16 mma, 3-stage cp.async ring, full-ldmatrix fragments)
    {
        dim3 blk(256);
        dim3 g2(FEATD / 128, M_TOK / 128);   // (4, 512)
        gemm_f16<<<g2, blk, G_SMEM>>>(p_h1h, p_w2p, b2, p_h2h, M_TOK, H1D,  FEATD, 1, 1);
        gemm_f16<<<g2, blk, G_SMEM>>>(p_h2h, p_w3p, b3, p_h3h, M_TOK, FEATD, FEATD, 1, 1);
        gemm_f16<<<g2, blk, G_SMEM>>>(p_h3h, p_w4p, b4, d_out, M_TOK, FEATD, FEATD, 0, 0);
    }
}